// round 3
// baseline (speedup 1.0000x reference)
#include <cuda_runtime.h>
#include <cstddef>

// Causal GQA prefill attention, fp32. B=2,S=2048,H=32,KVH=8,D=128.
// input_pos = arange(S) + zero caches => plain causal attention.
// Flash-attention SIMT kernel using packed fma.rn.f32x2 for 2x fp32 rate.

#define NTH 256
typedef unsigned long long ull;

union F4U { float4 f; ull u[2]; };
union U2F { ull u; float2 f; };

__device__ __forceinline__ ull fma2(ull a, ull b, ull c) {
    ull d; asm("fma.rn.f32x2 %0, %1, %2, %3;" : "=l"(d) : "l"(a), "l"(b), "l"(c));
    return d;
}
__device__ __forceinline__ ull mul2(ull a, ull b) {
    ull d; asm("mul.rn.f32x2 %0, %1, %2;" : "=l"(d) : "l"(a), "l"(b));
    return d;
}
__device__ __forceinline__ ull pack2(float x) {
    ull d; asm("mov.b64 %0, {%1, %1};" : "=l"(d) : "r"(__float_as_uint(x)));
    return d;
}
// swizzled float4 index in a 64x32-chunk tile (decorrelates stride-4-row reads)
__device__ __forceinline__ int sw(int row, int c) { return (row << 5) + (c ^ ((row >> 2) & 7)); }

// dynamic smem layout (floats):
//   Qs4 @ 0      : 2048 float4 (8192 f)
//   Ks4 @ 8192   : 2048 float4 (8192 f)
//   Vs2 @ 16384  : 64*66 float2 (8448 f)   row-major, pad 66
//   P   @ 24832  : 64*68 float (4352 f)
#define SMEM_FLOATS 29184

__global__ void __launch_bounds__(NTH, 1)
fa_fwd_kernel(const float* __restrict__ q, const float* __restrict__ k,
              const float* __restrict__ v, float* __restrict__ out)
{
    extern __shared__ float sm[];
    float4* Qs4 = (float4*)sm;
    float4* Ks4 = (float4*)(sm + 8192);
    float2* Vs2 = (float2*)(sm + 16384);
    float*  P   = sm + 24832;

    const int qt  = (int)gridDim.x - 1 - (int)blockIdx.x;  // big tiles first
    const int h   = blockIdx.y;
    const int b   = blockIdx.z;
    const int kvh = h >> 2;
    const int tid = threadIdx.x;
    const int tx  = tid & 15;
    const int ty  = tid >> 4;
    const int i0  = ty << 2;
    const int j0  = tx << 2;
    const float scale = 0.08838834764831845f;  // 1/sqrt(128)

    // Q tile (64 x 128) -> swizzled float4 chunks
    {
        const float* qb = q + (((size_t)b * 2048 + (size_t)qt * 64) * 32 + h) * 128;
        #pragma unroll
        for (int it = 0; it < 8; ++it) {
            int idx = it * NTH + tid, row = idx >> 5, c = idx & 31;
            Qs4[sw(row, c)] = *(const float4*)(qb + (size_t)row * 4096 + c * 4);
        }
    }

    float m_i[4], l_i[4];
    ull o2[4][4];  // [row][dpair kk] dims: 2*(tx+16kk), +1
    #pragma unroll
    for (int i = 0; i < 4; ++i) {
        m_i[i] = -1e30f; l_i[i] = 0.0f;
        #pragma unroll
        for (int kk = 0; kk < 4; ++kk) o2[i][kk] = 0ull;
    }

    const float* kb0 = k + ((size_t)b * 8 + kvh) * 2048 * 128;
    const float* vb0 = v + ((size_t)b * 8 + kvh) * 2048 * 128;

    for (int kt = 0; kt <= qt; ++kt) {
        __syncthreads();
        const float* kb = kb0 + (size_t)kt * 64 * 128;
        const float* vb = vb0 + (size_t)kt * 64 * 128;
        #pragma unroll
        for (int it = 0; it < 8; ++it) {
            int idx = it * NTH + tid, row = idx >> 5, c = idx & 31;
            Ks4[sw(row, c)] = *(const float4*)(kb + idx * 4);
        }
        // V tile: 64 rows x 128 floats = 2048 float4; scatter into padded float2 rows
        #pragma unroll
        for (int it = 0; it < 8; ++it) {
            int idx = it * NTH + tid, row = idx >> 5, c4 = idx & 31;
            float4 a = *(const float4*)(vb + idx * 4);
            Vs2[row * 66 + 2 * c4]     = make_float2(a.x, a.y);
            Vs2[row * 66 + 2 * c4 + 1] = make_float2(a.z, a.w);
        }
        __syncthreads();

        // ---- S = Q K^T, packed over d ----
        ull acc[4][4];
        #pragma unroll
        for (int i = 0; i < 4; ++i)
            #pragma unroll
            for (int j = 0; j < 4; ++j) acc[i][j] = 0ull;

        #pragma unroll 4
        for (int c = 0; c < 32; ++c) {
            F4U qf[4], kf[4];
            #pragma unroll
            for (int r = 0; r < 4; ++r) qf[r].f = Qs4[sw(i0 + r, c)];
            #pragma unroll
            for (int r = 0; r < 4; ++r) kf[r].f = Ks4[sw(j0 + r, c)];
            #pragma unroll
            for (int i = 0; i < 4; ++i)
                #pragma unroll
                for (int j = 0; j < 4; ++j) {
                    acc[i][j] = fma2(qf[i].u[0], kf[j].u[0], acc[i][j]);
                    acc[i][j] = fma2(qf[i].u[1], kf[j].u[1], acc[i][j]);
                }
        }

        float s[4][4];
        #pragma unroll
        for (int i = 0; i < 4; ++i)
            #pragma unroll
            for (int j = 0; j < 4; ++j) {
                U2F t; t.u = acc[i][j];
                s[i][j] = (t.f.x + t.f.y) * scale;
            }
        if (kt == qt) {
            #pragma unroll
            for (int i = 0; i < 4; ++i)
                #pragma unroll
                for (int j = 0; j < 4; ++j)
                    if (j0 + j > i0 + i) s[i][j] = -1e30f;
        }

        // ---- online softmax (16 lanes per row group) ----
        #pragma unroll
        for (int i = 0; i < 4; ++i) {
            float mx = fmaxf(fmaxf(s[i][0], s[i][1]), fmaxf(s[i][2], s[i][3]));
            #pragma unroll
            for (int m = 1; m < 16; m <<= 1)
                mx = fmaxf(mx, __shfl_xor_sync(0xffffffffu, mx, m));
            float m_new = fmaxf(m_i[i], mx);
            float alpha = __expf(m_i[i] - m_new);
            float p0 = __expf(s[i][0] - m_new), p1 = __expf(s[i][1] - m_new);
            float p2 = __expf(s[i][2] - m_new), p3 = __expf(s[i][3] - m_new);
            float rs = (p0 + p1) + (p2 + p3);
            #pragma unroll
            for (int m = 1; m < 16; m <<= 1)
                rs += __shfl_xor_sync(0xffffffffu, rs, m);
            l_i[i] = l_i[i] * alpha + rs;
            m_i[i] = m_new;
            ull a2 = pack2(alpha);
            #pragma unroll
            for (int kk = 0; kk < 4; ++kk) o2[i][kk] = mul2(o2[i][kk], a2);
            *(float4*)&P[(i0 + i) * 68 + j0] = make_float4(p0, p1, p2, p3);
        }
        __syncthreads();

        // ---- O += P V, packed over d ----
        #pragma unroll 2
        for (int j = 0; j < 64; ++j) {
            ull pp[4];
            #pragma unroll
            for (int i = 0; i < 4; ++i) pp[i] = pack2(P[(i0 + i) * 68 + j]);
            U2F vv[4];
            #pragma unroll
            for (int kk = 0; kk < 4; ++kk) vv[kk].f = Vs2[j * 66 + tx + 16 * kk];
            #pragma unroll
            for (int i = 0; i < 4; ++i)
                #pragma unroll
                for (int kk = 0; kk < 4; ++kk)
                    o2[i][kk] = fma2(pp[i], vv[kk].u, o2[i][kk]);
        }
    }

    // ---- write out: out[b, row, h*128 + d] ----
    #pragma unroll
    for (int i = 0; i < 4; ++i) {
        float inv = 1.0f / l_i[i];
        size_t base = ((size_t)b * 2048 + (size_t)qt * 64 + i0 + i) * 4096 + h * 128;
        #pragma unroll
        for (int kk = 0; kk < 4; ++kk) {
            U2F t; t.u = o2[i][kk];
            t.f.x *= inv; t.f.y *= inv;
            *(float2*)(out + base + 2 * (tx + 16 * kk)) = t.f;
        }
    }
}

extern "C" void kernel_launch(void* const* d_in, const int* in_sizes, int n_in,
                              void* d_out, int out_size) {
    // inputs: input_pos, q, k, v, ... ; find q by its unique element count
    int iq = -1;
    for (int i = 0; i < n_in; ++i)
        if (in_sizes[i] == 16777216) { iq = i; break; }
    if (iq < 0) iq = 1;
    const float* q = (const float*)d_in[iq];
    const float* k = (const float*)d_in[iq + 1];
    const float* v = (const float*)d_in[iq + 2];
    float* out = (float*)d_out;

    cudaFuncSetAttribute(fa_fwd_kernel,
                         cudaFuncAttributeMaxDynamicSharedMemorySize,
                         SMEM_FLOATS * 4);
    dim3 grid(32, 32, 2);  // qt tiles, H, B
    fa_fwd_kernel<<<grid, NTH, SMEM_FLOATS * 4>>>(q, k, v, out);
}